// round 1
// baseline (speedup 1.0000x reference)
#include <cuda_runtime.h>
#include <math.h>

// Problem constants
#define B_   4
#define S_   1024
#define E_   1024
#define D_   1024
#define H_   16
#define DH_  64
#define DFF_ 4096
#define MROWS (B_*S_)   // 4096

// ---------------- scratch (device globals; no runtime allocation) ----------
__device__ float g_qkv   [(size_t)MROWS * 3 * D_];       // 48 MB
__device__ float g_scores[(size_t)B_ * H_ * S_ * S_];    // 256 MB
__device__ float g_attn  [(size_t)MROWS * D_];           // 16 MB
__device__ float g_tmp   [(size_t)MROWS * D_];
__device__ float g_h1    [(size_t)MROWS * D_];
__device__ float g_h2    [(size_t)MROWS * D_];
__device__ float g_q     [(size_t)MROWS * D_];
__device__ float g_k     [(size_t)B_ * E_ * D_];
__device__ float g_v     [(size_t)B_ * E_ * D_];
__device__ float g_ffn1  [(size_t)MROWS * DFF_];         // 64 MB

// ---------------- generic GEMM: C[M,N] = A[M,K] @ W[K,N] + bias, opt GELU ----
#define BM 64
#define BN 64
#define BK 16

__global__ __launch_bounds__(256)
void gemm_kernel(const float* __restrict__ A, const float* __restrict__ W,
                 const float* __restrict__ bias, float* __restrict__ C,
                 int M, int N, int K, int act)
{
    __shared__ float As[BK][BM];
    __shared__ float Ws[BK][BN];
    const int tid = threadIdx.x;
    const int tx = tid & 15;          // 0..15
    const int ty = tid >> 4;          // 0..15
    const int rowBase = blockIdx.y * BM;
    const int colBase = blockIdx.x * BN;

    float acc[4][4] = {};

    for (int k0 = 0; k0 < K; k0 += BK) {
        // A tile: BM x BK = 1024 elems, 4 per thread
        #pragma unroll
        for (int i = 0; i < 4; i++) {
            int e  = tid + i * 256;
            int m  = e >> 4;          // /BK
            int kk = e & 15;
            As[kk][m] = A[(size_t)(rowBase + m) * K + k0 + kk];
        }
        // W tile: BK x BN = 1024 elems
        #pragma unroll
        for (int i = 0; i < 4; i++) {
            int e  = tid + i * 256;
            int kk = e >> 6;          // /BN
            int n  = e & 63;
            Ws[kk][n] = W[(size_t)(k0 + kk) * N + colBase + n];
        }
        __syncthreads();
        #pragma unroll
        for (int kk = 0; kk < BK; kk++) {
            float4 a4 = *reinterpret_cast<const float4*>(&As[kk][ty * 4]);
            float4 b4 = *reinterpret_cast<const float4*>(&Ws[kk][tx * 4]);
            float a[4] = {a4.x, a4.y, a4.z, a4.w};
            float b[4] = {b4.x, b4.y, b4.z, b4.w};
            #pragma unroll
            for (int i = 0; i < 4; i++)
                #pragma unroll
                for (int j = 0; j < 4; j++)
                    acc[i][j] += a[i] * b[j];
        }
        __syncthreads();
    }

    #pragma unroll
    for (int i = 0; i < 4; i++) {
        int m = rowBase + ty * 4 + i;
        #pragma unroll
        for (int j = 0; j < 4; j++) {
            int n = colBase + tx * 4 + j;
            float v = acc[i][j] + bias[n];
            if (act == 1)  // exact GELU
                v = 0.5f * v * (1.0f + erff(v * 0.70710678118654752f));
            C[(size_t)m * N + n] = v;
        }
    }
}

// ---------------- attention scores:  S[bh,q,k] = Q.K / 8  (+causal) --------
// Q elem: Q[(b*1024+q)*qrs + h*qhs + d]; K elem: K[(b*1024+k)*krs + h*khs + kadd + d]
__global__ __launch_bounds__(256)
void scores_kernel(const float* __restrict__ Q, const float* __restrict__ K,
                   float* __restrict__ Sc,
                   int qrs, int krs, int qhs, int khs, int kadd, int causal)
{
    const int bh = blockIdx.z;
    const int b  = bh >> 4;
    const int h  = bh & 15;
    const int q0 = blockIdx.y * 32;
    const int k0 = blockIdx.x * 32;
    const int tx = threadIdx.x;   // 0..15
    const int ty = threadIdx.y;   // 0..15

    if (causal && k0 > q0 + 31) {   // fully masked tile
        #pragma unroll
        for (int i = 0; i < 2; i++)
            #pragma unroll
            for (int j = 0; j < 2; j++)
                Sc[((size_t)bh * 1024 + q0 + ty + 16 * i) * 1024 + k0 + tx + 16 * j] = -INFINITY;
        return;
    }

    __shared__ float Qs[32][65];
    __shared__ float Ks[32][65];
    const int tid = ty * 16 + tx;
    #pragma unroll
    for (int i = 0; i < 8; i++) {
        int e = tid + i * 256;     // 0..2047
        int r = e >> 6;
        int d = e & 63;
        Qs[r][d] = Q[(size_t)(b * 1024 + q0 + r) * qrs + h * qhs + d];
        Ks[r][d] = K[(size_t)(b * 1024 + k0 + r) * krs + h * khs + kadd + d];
    }
    __syncthreads();

    float acc00 = 0, acc01 = 0, acc10 = 0, acc11 = 0;
    #pragma unroll
    for (int dd = 0; dd < 64; dd++) {
        float a0 = Qs[ty][dd],      a1 = Qs[ty + 16][dd];
        float b0 = Ks[tx][dd],      b1 = Ks[tx + 16][dd];
        acc00 += a0 * b0;  acc01 += a0 * b1;
        acc10 += a1 * b0;  acc11 += a1 * b1;
    }

    float r[2][2] = {{acc00, acc01}, {acc10, acc11}};
    #pragma unroll
    for (int i = 0; i < 2; i++) {
        int qq = q0 + ty + 16 * i;
        #pragma unroll
        for (int j = 0; j < 2; j++) {
            int kk = k0 + tx + 16 * j;
            float v = r[i][j] * 0.125f;
            if (causal && kk > qq) v = -INFINITY;
            Sc[((size_t)bh * 1024 + qq) * 1024 + kk] = v;
        }
    }
}

// ---------------- softmax over rows of length 1024 --------------------------
__global__ __launch_bounds__(256)
void softmax_kernel(float* __restrict__ Sc)
{
    const size_t row = blockIdx.x;
    float* p = Sc + row * 1024;
    const int t = threadIdx.x;
    __shared__ float red[8];

    float v[4];
    float mx = -INFINITY;
    #pragma unroll
    for (int i = 0; i < 4; i++) { v[i] = p[t + i * 256]; mx = fmaxf(mx, v[i]); }
    #pragma unroll
    for (int o = 16; o; o >>= 1) mx = fmaxf(mx, __shfl_xor_sync(~0u, mx, o));
    if ((t & 31) == 0) red[t >> 5] = mx;
    __syncthreads();
    float m = red[0];
    #pragma unroll
    for (int i = 1; i < 8; i++) m = fmaxf(m, red[i]);
    __syncthreads();

    float s = 0;
    #pragma unroll
    for (int i = 0; i < 4; i++) { v[i] = __expf(v[i] - m); s += v[i]; }
    #pragma unroll
    for (int o = 16; o; o >>= 1) s += __shfl_xor_sync(~0u, s, o);
    if ((t & 31) == 0) red[t >> 5] = s;
    __syncthreads();
    float tot = 0;
    #pragma unroll
    for (int i = 0; i < 8; i++) tot += red[i];
    float inv = 1.0f / tot;
    #pragma unroll
    for (int i = 0; i < 4; i++) p[t + i * 256] = v[i] * inv;
}

// ---------------- attn @ V:  out[(b*1024+q)*D + h*64 + d] -------------------
// V elem: V[(b*1024+k)*vrs + h*vhs + vadd + d]
__global__ __launch_bounds__(1024)
void av_kernel(const float* __restrict__ P, const float* __restrict__ V,
               float* __restrict__ out, int vrs, int vhs, int vadd, int causal)
{
    const int bh = blockIdx.z;
    const int b  = bh >> 4;
    const int h  = bh & 15;
    const int q0 = blockIdx.x * 32;
    const int tx = threadIdx.x;   // 0..31
    const int ty = threadIdx.y;   // 0..31

    __shared__ float Ps[32][33];
    __shared__ float Vs[32][64];

    float acc0 = 0, acc1 = 0;
    const int kend = causal ? (q0 + 32) : 1024;
    for (int k0 = 0; k0 < kend; k0 += 32) {
        Ps[ty][tx] = P[((size_t)bh * 1024 + q0 + ty) * 1024 + k0 + tx];
        int idx = ty * 32 + tx;
        #pragma unroll
        for (int i = 0; i < 2; i++) {
            int e = idx + i * 1024;   // 0..2047
            int r = e >> 6;
            int d = e & 63;
            Vs[r][d] = V[(size_t)(b * 1024 + k0 + r) * vrs + h * vhs + vadd + d];
        }
        __syncthreads();
        #pragma unroll
        for (int kk = 0; kk < 32; kk++) {
            float pr = Ps[ty][kk];
            acc0 += pr * Vs[kk][tx];
            acc1 += pr * Vs[kk][tx + 32];
        }
        __syncthreads();
    }
    size_t o = (size_t)(b * 1024 + q0 + ty) * D_ + h * 64;
    out[o + tx]      = acc0;
    out[o + tx + 32] = acc1;
}

// ---------------- fused residual-add + LayerNorm ---------------------------
__global__ __launch_bounds__(256)
void add_ln_kernel(const float* __restrict__ resid, const float* __restrict__ y,
                   const float* __restrict__ g, const float* __restrict__ be,
                   float* __restrict__ out)
{
    const size_t base = (size_t)blockIdx.x * 1024;
    const int t = threadIdx.x;
    __shared__ float red[8];

    float v[4];
    float s = 0;
    #pragma unroll
    for (int i = 0; i < 4; i++) {
        v[i] = resid[base + t + i * 256] + y[base + t + i * 256];
        s += v[i];
    }
    #pragma unroll
    for (int o = 16; o; o >>= 1) s += __shfl_xor_sync(~0u, s, o);
    if ((t & 31) == 0) red[t >> 5] = s;
    __syncthreads();
    float tot = 0;
    #pragma unroll
    for (int i = 0; i < 8; i++) tot += red[i];
    float mean = tot * (1.0f / 1024.0f);
    __syncthreads();

    float vs = 0;
    #pragma unroll
    for (int i = 0; i < 4; i++) { float d = v[i] - mean; vs += d * d; }
    #pragma unroll
    for (int o = 16; o; o >>= 1) vs += __shfl_xor_sync(~0u, vs, o);
    if ((t & 31) == 0) red[t >> 5] = vs;
    __syncthreads();
    tot = 0;
    #pragma unroll
    for (int i = 0; i < 8; i++) tot += red[i];
    float inv = rsqrtf(tot * (1.0f / 1024.0f) + 1e-5f);

    #pragma unroll
    for (int i = 0; i < 4; i++) {
        int c = t + i * 256;
        out[base + c] = g[c] * (v[i] - mean) * inv + be[c];
    }
}

// ---------------- launch ----------------------------------------------------
extern "C" void kernel_launch(void* const* d_in, const int* in_sizes, int n_in,
                              void* d_out, int out_size)
{
    const float* x      = (const float*)d_in[0];
    const float* enc_x  = (const float*)d_in[1];
    const float* w_qkv  = (const float*)d_in[2];
    const float* b_qkv  = (const float*)d_in[3];
    const float* w_sa_o = (const float*)d_in[4];
    const float* b_sa_o = (const float*)d_in[5];
    const float* w_q    = (const float*)d_in[6];
    const float* b_q    = (const float*)d_in[7];
    const float* w_k    = (const float*)d_in[8];
    const float* b_k    = (const float*)d_in[9];
    const float* w_v    = (const float*)d_in[10];
    const float* b_v    = (const float*)d_in[11];
    const float* w_ca_o = (const float*)d_in[12];
    const float* b_ca_o = (const float*)d_in[13];
    const float* w1     = (const float*)d_in[14];
    const float* b1     = (const float*)d_in[15];
    const float* w2     = (const float*)d_in[16];
    const float* b2     = (const float*)d_in[17];
    const float* g1     = (const float*)d_in[18];
    const float* be1    = (const float*)d_in[19];
    const float* g2     = (const float*)d_in[20];
    const float* be2    = (const float*)d_in[21];
    const float* g3     = (const float*)d_in[22];
    const float* be3    = (const float*)d_in[23];
    float* out = (float*)d_out;

    float *p_qkv, *p_sc, *p_attn, *p_tmp, *p_h1, *p_h2, *p_q, *p_k, *p_v, *p_f1;
    cudaGetSymbolAddress((void**)&p_qkv,  g_qkv);
    cudaGetSymbolAddress((void**)&p_sc,   g_scores);
    cudaGetSymbolAddress((void**)&p_attn, g_attn);
    cudaGetSymbolAddress((void**)&p_tmp,  g_tmp);
    cudaGetSymbolAddress((void**)&p_h1,   g_h1);
    cudaGetSymbolAddress((void**)&p_h2,   g_h2);
    cudaGetSymbolAddress((void**)&p_q,    g_q);
    cudaGetSymbolAddress((void**)&p_k,    g_k);
    cudaGetSymbolAddress((void**)&p_v,    g_v);
    cudaGetSymbolAddress((void**)&p_f1,   g_ffn1);

    const dim3 blk256(256);
    const dim3 sblk(16, 16);
    const dim3 sgrd(32, 32, B_ * H_);
    const dim3 avblk(32, 32);
    const dim3 avgrd(32, 1, B_ * H_);

    // ---- masked self-attention ----
    gemm_kernel<<<dim3(3 * D_ / BN, MROWS / BM), blk256>>>(x, w_qkv, b_qkv, p_qkv,
                                                           MROWS, 3 * D_, D_, 0);
    scores_kernel<<<sgrd, sblk>>>(p_qkv, p_qkv, p_sc, 3 * D_, 3 * D_, 192, 192, 64, 1);
    softmax_kernel<<<B_ * H_ * S_, blk256>>>(p_sc);
    av_kernel<<<avgrd, avblk>>>(p_sc, p_qkv, p_attn, 3 * D_, 192, 128, 1);
    gemm_kernel<<<dim3(D_ / BN, MROWS / BM), blk256>>>(p_attn, w_sa_o, b_sa_o, p_tmp,
                                                       MROWS, D_, D_, 0);
    add_ln_kernel<<<MROWS, blk256>>>(x, p_tmp, g1, be1, p_h1);

    // ---- cross-attention ----
    gemm_kernel<<<dim3(D_ / BN, MROWS / BM), blk256>>>(p_h1, w_q, b_q, p_q, MROWS, D_, D_, 0);
    gemm_kernel<<<dim3(D_ / BN, MROWS / BM), blk256>>>(enc_x, w_k, b_k, p_k, B_ * E_, D_, D_, 0);
    gemm_kernel<<<dim3(D_ / BN, MROWS / BM), blk256>>>(enc_x, w_v, b_v, p_v, B_ * E_, D_, D_, 0);
    scores_kernel<<<sgrd, sblk>>>(p_q, p_k, p_sc, D_, D_, 64, 64, 0, 0);
    softmax_kernel<<<B_ * H_ * S_, blk256>>>(p_sc);
    av_kernel<<<avgrd, avblk>>>(p_sc, p_v, p_attn, D_, 64, 0, 0);
    gemm_kernel<<<dim3(D_ / BN, MROWS / BM), blk256>>>(p_attn, w_ca_o, b_ca_o, p_tmp,
                                                       MROWS, D_, D_, 0);
    add_ln_kernel<<<MROWS, blk256>>>(p_h1, p_tmp, g2, be2, p_h2);

    // ---- FFN ----
    gemm_kernel<<<dim3(DFF_ / BN, MROWS / BM), blk256>>>(p_h2, w1, b1, p_f1,
                                                         MROWS, DFF_, D_, 1);
    gemm_kernel<<<dim3(D_ / BN, MROWS / BM), blk256>>>(p_f1, w2, b2, p_tmp,
                                                       MROWS, D_, DFF_, 0);
    add_ln_kernel<<<MROWS, blk256>>>(p_h2, p_tmp, g3, be3, out);
}

// round 5
// speedup vs baseline: 2.6921x; 2.6921x over previous
#include <cuda_runtime.h>
#include <cuda_fp16.h>
#include <math.h>
#include <stdint.h>

// Problem constants
#define B_   4
#define S_   1024
#define E_   1024
#define D_   1024
#define H_   16
#define DH_  64
#define DFF_ 4096
#define MROWS (B_*S_)   // 4096

__device__ __forceinline__ uint32_t smem_u32(const void* p) {
    uint32_t a;
    asm("{ .reg .u64 t; cvta.to.shared.u64 t, %1; cvt.u32.u64 %0, t; }"
        : "=r"(a) : "l"(p));
    return a;
}

// ============================= scratch =====================================
__device__ float  g_qkv   [(size_t)MROWS * 3 * D_];
__device__ float  g_scores[(size_t)B_ * H_ * S_ * S_];
__device__ float  g_attn  [(size_t)MROWS * D_];
__device__ float  g_tmp   [(size_t)MROWS * D_];
__device__ float  g_h1    [(size_t)MROWS * D_];
__device__ float  g_h2    [(size_t)MROWS * D_];
__device__ float  g_q     [(size_t)MROWS * D_];
__device__ float  g_k     [(size_t)B_ * E_ * D_];
__device__ float  g_v     [(size_t)B_ * E_ * D_];

// fp16 buffers
__device__ __half g_x16   [(size_t)MROWS * D_];
__device__ __half g_ex16  [(size_t)B_ * E_ * D_];
__device__ __half g_attn16[(size_t)MROWS * D_];
__device__ __half g_h16   [(size_t)MROWS * D_];
__device__ __half g_f116  [(size_t)MROWS * DFF_];
// transposed fp16 weights [N,K]
__device__ __half g_wqkvT [(size_t)3 * D_ * D_];
__device__ __half g_wsaoT [(size_t)D_ * D_];
__device__ __half g_wqT   [(size_t)D_ * D_];
__device__ __half g_wkT   [(size_t)D_ * D_];
__device__ __half g_wvT   [(size_t)D_ * D_];
__device__ __half g_wcaoT [(size_t)D_ * D_];
__device__ __half g_w1T   [(size_t)D_ * DFF_];
__device__ __half g_w2T   [(size_t)DFF_ * D_];

// ======================== conversion kernels ===============================
__global__ __launch_bounds__(256)
void f32_to_f16_kernel(const float* __restrict__ in, __half* __restrict__ out, int n)
{
    int i = blockIdx.x * 256 + threadIdx.x;
    int stride = gridDim.x * 256;
    for (; i < n; i += stride) out[i] = __float2half(in[i]);
}

// W[K,N] fp32 -> Wt[N,K] fp16
__global__ __launch_bounds__(1024)
void transpose_f16_kernel(const float* __restrict__ W, __half* __restrict__ Wt,
                          int K, int N)
{
    __shared__ float t[32][33];
    int k = blockIdx.y * 32 + threadIdx.y;
    int n = blockIdx.x * 32 + threadIdx.x;
    t[threadIdx.y][threadIdx.x] = W[(size_t)k * N + n];
    __syncthreads();
    int nn = blockIdx.x * 32 + threadIdx.y;
    int kk = blockIdx.y * 32 + threadIdx.x;
    Wt[(size_t)nn * K + kk] = __float2half(t[threadIdx.x][threadIdx.y]);
}

// ===================== mma.sync fp16 GEMM ==================================
// C[M,N] = A[M,K] (fp16 row-major) @ Bt[N,K]^T (fp16) + bias ; opt GELU.
// CTA tile 128x128x32, 8 warps (4 m x 2 n), warp tile 32x64.
// SMEM rows padded to 40 halfs (80 B) => ldmatrix conflict-free.
#define TM 128
#define TN 128
#define KC 32
#define PAD 40

__device__ __forceinline__ void ldmx4(uint32_t* r, uint32_t addr) {
    asm volatile("ldmatrix.sync.aligned.m8n8.x4.shared.b16 {%0,%1,%2,%3}, [%4];"
                 : "=r"(r[0]), "=r"(r[1]), "=r"(r[2]), "=r"(r[3]) : "r"(addr));
}
__device__ __forceinline__ void mma16816(float* c, const uint32_t* a, const uint32_t* b) {
    asm volatile("mma.sync.aligned.m16n8k16.row.col.f32.f16.f16.f32 "
                 "{%0,%1,%2,%3}, {%4,%5,%6,%7}, {%8,%9}, {%0,%1,%2,%3};"
                 : "+f"(c[0]), "+f"(c[1]), "+f"(c[2]), "+f"(c[3])
                 : "r"(a[0]), "r"(a[1]), "r"(a[2]), "r"(a[3]), "r"(b[0]), "r"(b[1]));
}
#define CP_ASYNC16(smem, gmem) \
    asm volatile("cp.async.cg.shared.global [%0], [%1], 16;" \
                 :: "r"(smem), "l"(gmem) : "memory")
#define CP_COMMIT() asm volatile("cp.async.commit_group;" ::: "memory")
#define CP_WAIT0()  asm volatile("cp.async.wait_group 0;" ::: "memory")

__global__ void __launch_bounds__(256, 2)
gemm_tc(const __half* __restrict__ A, const __half* __restrict__ Bt,
        const float* __restrict__ bias, float* __restrict__ outf,
        __half* __restrict__ outh, int M, int N, int K, int act)
{
    __shared__ __align__(16) __half sA[2][TM][PAD];
    __shared__ __align__(16) __half sB[2][TN][PAD];

    const int tid  = threadIdx.x;
    const int lane = tid & 31;
    const int wid  = tid >> 5;
    const int wm   = wid & 3;          // 0..3  -> 32-row slice
    const int wn   = wid >> 2;         // 0..1  -> 64-col slice
    const int m0 = blockIdx.y * TM;
    const int n0 = blockIdx.x * TN;

    float acc[2][8][4];
    #pragma unroll
    for (int i = 0; i < 2; i++)
        #pragma unroll
        for (int j = 0; j < 8; j++)
            #pragma unroll
            for (int q = 0; q < 4; q++) acc[i][j][q] = 0.f;

    // per-thread copy coords: 512 chunks of 16B per tile, 2 per thread
    const int r0c = tid >> 1;                    // 0..127
    const int j0c = (tid & 1) * 2;               // 0 or 2  (two consecutive chunks)

    const int nch = K / KC;

    // prologue: stage 0
    {
        const __half* Ag = A  + (size_t)m0 * K;
        const __half* Bg = Bt + (size_t)n0 * K;
        #pragma unroll
        for (int j = 0; j < 2; j++) {
            uint32_t sa = smem_u32(&sA[0][r0c][(j0c + j) * 8]);
            uint32_t sb = smem_u32(&sB[0][r0c][(j0c + j) * 8]);
            CP_ASYNC16(sa, Ag + (size_t)r0c * K + (j0c + j) * 8);
            CP_ASYNC16(sb, Bg + (size_t)r0c * K + (j0c + j) * 8);
        }
        CP_COMMIT();
    }

    for (int c = 0; c < nch; c++) {
        CP_WAIT0();
        __syncthreads();

        if (c + 1 < nch) {
            const int st = (c + 1) & 1;
            const __half* Ag = A  + (size_t)m0 * K + (c + 1) * KC;
            const __half* Bg = Bt + (size_t)n0 * K + (c + 1) * KC;
            #pragma unroll
            for (int j = 0; j < 2; j++) {
                uint32_t sa = smem_u32(&sA[st][r0c][(j0c + j) * 8]);
                uint32_t sb = smem_u32(&sB[st][r0c][(j0c + j) * 8]);
                CP_ASYNC16(sa, Ag + (size_t)r0c * K + (j0c + j) * 8);
                CP_ASYNC16(sb, Bg + (size_t)r0c * K + (j0c + j) * 8);
            }
            CP_COMMIT();
        }

        const int st = c & 1;
        #pragma unroll
        for (int ks = 0; ks < KC; ks += 16) {
            uint32_t afr[2][4];
            #pragma unroll
            for (int mi = 0; mi < 2; mi++) {
                int r  = wm * 32 + mi * 16 + (lane & 15);
                int cc = ks + ((lane >> 4) << 3);
                ldmx4(afr[mi], smem_u32(&sA[st][r][cc]));
            }
            uint32_t bfr[4][4];
            #pragma unroll
            for (int nj = 0; nj < 4; nj++) {
                int r  = wn * 64 + nj * 16 + ((lane & 7) | ((lane & 16) >> 1));
                int cc = ks + (((lane >> 3) & 1) << 3);
                ldmx4(bfr[nj], smem_u32(&sB[st][r][cc]));
            }
            #pragma unroll
            for (int mi = 0; mi < 2; mi++)
                #pragma unroll
                for (int nj = 0; nj < 8; nj++)
                    mma16816(acc[mi][nj], afr[mi], &bfr[nj >> 1][(nj & 1) * 2]);
        }
        __syncthreads();
    }

    // epilogue: bias (+GELU), write fp32 and/or fp16
    #pragma unroll
    for (int mi = 0; mi < 2; mi++) {
        #pragma unroll
        for (int rr = 0; rr < 2; rr++) {
            const int row = m0 + wm * 32 + mi * 16 + rr * 8 + (lane >> 2);
            #pragma unroll
            for (int nj = 0; nj < 8; nj++) {
                const int col = n0 + wn * 64 + nj * 8 + (lane & 3) * 2;
                float v0 = acc[mi][nj][rr * 2 + 0] + bias[col];
                float v1 = acc[mi][nj][rr * 2 + 1] + bias[col + 1];
                if (act) {
                    v0 = 0.5f * v0 * (1.0f + erff(v0 * 0.70710678118654752f));
                    v1 = 0.5f * v1 * (1.0f + erff(v1 * 0.70710678118654752f));
                }
                if (outf)
                    *(float2*)(outf + (size_t)row * N + col) = make_float2(v0, v1);
                if (outh)
                    *(__half2*)(outh + (size_t)row * N + col) = __floats2half2_rn(v0, v1);
            }
        }
    }
}

// ================== fp32 attention kernels (unchanged) =====================
__global__ __launch_bounds__(256)
void scores_kernel(const float* __restrict__ Q, const float* __restrict__ K,
                   float* __restrict__ Sc,
                   int qrs, int krs, int qhs, int khs, int kadd, int causal)
{
    const int bh = blockIdx.z;
    const int b  = bh >> 4;
    const int h  = bh & 15;
    const int q0 = blockIdx.y * 32;
    const int k0 = blockIdx.x * 32;
    const int tx = threadIdx.x;
    const int ty = threadIdx.y;

    if (causal && k0 > q0 + 31) {
        #pragma unroll
        for (int i = 0; i < 2; i++)
            #pragma unroll
            for (int j = 0; j < 2; j++)
                Sc[((size_t)bh * 1024 + q0 + ty + 16 * i) * 1024 + k0 + tx + 16 * j] = -INFINITY;
        return;
    }

    __shared__ float Qs[32][65];
    __shared__ float Ks[32][65];
    const int tid = ty * 16 + tx;
    #pragma unroll
    for (int i = 0; i < 8; i++) {
        int e = tid + i * 256;
        int r = e >> 6;
        int d = e & 63;
        Qs[r][d] = Q[(size_t)(b * 1024 + q0 + r) * qrs + h * qhs + d];
        Ks[r][d] = K[(size_t)(b * 1024 + k0 + r) * krs + h * khs + kadd + d];
    }
    __syncthreads();

    float acc00 = 0, acc01 = 0, acc10 = 0, acc11 = 0;
    #pragma unroll
    for (int dd = 0; dd < 64; dd++) {
        float a0 = Qs[ty][dd],      a1 = Qs[ty + 16][dd];
        float b0 = Ks[tx][dd],      b1 = Ks[tx + 16][dd];
        acc00 += a0 * b0;  acc01 += a0 * b1;
        acc10 += a1 * b0;  acc11 += a1 * b1;
    }

    float r[2][2] = {{acc00, acc01}, {acc10, acc11}};
    #pragma unroll
    for (int i = 0; i < 2; i++) {
        int qq = q0 + ty + 16 * i;
        #pragma unroll
        for (int j = 0; j < 2; j++) {
            int kk = k0 + tx + 16 * j;
            float v = r[i][j] * 0.125f;
            if (causal && kk > qq) v = -INFINITY;
            Sc[((size_t)bh * 1024 + qq) * 1024 + kk] = v;
        }
    }
}

__global__ __launch_bounds__(256)
void softmax_kernel(float* __restrict__ Sc)
{
    const size_t row = blockIdx.x;
    float* p = Sc + row * 1024;
    const int t = threadIdx.x;
    __shared__ float red[8];

    float v[4];
    float mx = -INFINITY;
    #pragma unroll
    for (int i = 0; i < 4; i++) { v[i] = p[t + i * 256]; mx = fmaxf(mx, v[i]); }
    #pragma unroll
    for (int o = 16; o; o >>= 1) mx = fmaxf(mx, __shfl_xor_sync(~0u, mx, o));
    if ((t & 31) == 0) red[t >> 5] = mx;
    __syncthreads();
    float m = red[0];
    #pragma unroll
    for (int i = 1; i < 8; i++) m = fmaxf(m, red[i]);
    __syncthreads();

    float s = 0;
    #pragma unroll
    for (int i = 0; i < 4; i++) { v[i] = __expf(v[i] - m); s += v[i]; }
    #pragma unroll
    for (int o = 16; o; o >>= 1) s += __shfl_xor_sync(~0u, s, o);
    if ((t & 31) == 0) red[t >> 5] = s;
    __syncthreads();
    float tot = 0;
    #pragma unroll
    for (int i = 0; i < 8; i++) tot += red[i];
    float inv = 1.0f / tot;
    #pragma unroll
    for (int i = 0; i < 4; i++) p[t + i * 256] = v[i] * inv;
}

__global__ __launch_bounds__(1024)
void av_kernel(const float* __restrict__ P, const float* __restrict__ V,
               float* __restrict__ out, int vrs, int vhs, int vadd, int causal)
{
    const int bh = blockIdx.z;
    const int b  = bh >> 4;
    const int h  = bh & 15;
    const int q0 = blockIdx.x * 32;
    const int tx = threadIdx.x;
    const int ty = threadIdx.y;

    __shared__ float Ps[32][33];
    __shared__ float Vs[32][64];

    float acc0 = 0, acc1 = 0;
    const int kend = causal ? (q0 + 32) : 1024;
    for (int k0 = 0; k0 < kend; k0 += 32) {
        Ps[ty][tx] = P[((size_t)bh * 1024 + q0 + ty) * 1024 + k0 + tx];
        int idx = ty * 32 + tx;
        #pragma unroll
        for (int i = 0; i < 2; i++) {
            int e = idx + i * 1024;
            int r = e >> 6;
            int d = e & 63;
            Vs[r][d] = V[(size_t)(b * 1024 + k0 + r) * vrs + h * vhs + vadd + d];
        }
        __syncthreads();
        #pragma unroll
        for (int kk = 0; kk < 32; kk++) {
            float pr = Ps[ty][kk];
            acc0 += pr * Vs[kk][tx];
            acc1 += pr * Vs[kk][tx + 32];
        }
        __syncthreads();
    }
    size_t o = (size_t)(b * 1024 + q0 + ty) * D_ + h * 64;
    out[o + tx]      = acc0;
    out[o + tx + 32] = acc1;
}

__global__ __launch_bounds__(256)
void add_ln_kernel(const float* __restrict__ resid, const float* __restrict__ y,
                   const float* __restrict__ g, const float* __restrict__ be,
                   float* __restrict__ out)
{
    const size_t base = (size_t)blockIdx.x * 1024;
    const int t = threadIdx.x;
    __shared__ float red[8];

    float v[4];
    float s = 0;
    #pragma unroll
    for (int i = 0; i < 4; i++) {
        v[i] = resid[base + t + i * 256] + y[base + t + i * 256];
        s += v[i];
    }
    #pragma unroll
    for (int o = 16; o; o >>= 1) s += __shfl_xor_sync(~0u, s, o);
    if ((t & 31) == 0) red[t >> 5] = s;
    __syncthreads();
    float tot = 0;
    #pragma unroll
    for (int i = 0; i < 8; i++) tot += red[i];
    float mean = tot * (1.0f / 1024.0f);
    __syncthreads();

    float vs = 0;
    #pragma unroll
    for (int i = 0; i < 4; i++) { float d = v[i] - mean; vs += d * d; }
    #pragma unroll
    for (int o = 16; o; o >>= 1) vs += __shfl_xor_sync(~0u, vs, o);
    if ((t & 31) == 0) red[t >> 5] = vs;
    __syncthreads();
    tot = 0;
    #pragma unroll
    for (int i = 0; i < 8; i++) tot += red[i];
    float inv = rsqrtf(tot * (1.0f / 1024.0f) + 1e-5f);

    #pragma unroll
    for (int i = 0; i < 4; i++) {
        int c = t + i * 256;
        out[base + c] = g[c] * (v[i] - mean) * inv + be[c];
    }
}

// ================================ launch ===================================
extern "C" void kernel_launch(void* const* d_in, const int* in_sizes, int n_in,
                              void* d_out, int out_size)
{
    const float* x      = (const float*)d_in[0];
    const float* enc_x  = (const float*)d_in[1];
    const float* w_qkv  = (const float*)d_in[2];
    const float* b_qkv  = (const float*)d_in[3];
    const float* w_sa_o = (const float*)d_in[4];
    const float* b_sa_o = (const float*)d_in[5];
    const float* w_q    = (const float*)d_in[6];
    const float* b_q    = (const float*)d_in[7];
    const float* w_k    = (const float*)d_in[8];
    const float* b_k    = (const float*)d_in[9];
    const float* w_v    = (const float*)d_in[10];
    const float* b_v    = (const float*)d_in[11];
    const float* w_ca_o = (const float*)d_in[12];
    const float* b_ca_o = (const float*)d_in[13];
    const float* w1     = (const float*)d_in[14];
    const float* b1     = (const float*)d_in[15];
    const float* w2     = (const float*)d_in[16];
    const float* b2     = (const float*)d_in[17];
    const float* g1     = (const float*)d_in[18];
    const float* be1    = (const float*)d_in[19];
    const float* g2     = (const float*)d_in[20];
    const float* be2    = (const float*)d_in[21];
    const float* g3     = (const float*)d_in[22];
    const float* be3    = (const float*)d_in[23];
    float* out = (float*)d_out;

    float *p_qkv, *p_sc, *p_attn, *p_tmp, *p_h1, *p_h2, *p_q, *p_k, *p_v;
    cudaGetSymbolAddress((void**)&p_qkv,  g_qkv);
    cudaGetSymbolAddress((void**)&p_sc,   g_scores);
    cudaGetSymbolAddress((void**)&p_attn, g_attn);
    cudaGetSymbolAddress((void**)&p_tmp,  g_tmp);
    cudaGetSymbolAddress((void**)&p_h1,   g_h1);
    cudaGetSymbolAddress((void**)&p_h2,   g_h2);
    cudaGetSymbolAddress((void**)&p_q,    g_q);
    cudaGetSymbolAddress((void**)&p_k,    g_k);
    cudaGetSymbolAddress((void**)&p_v,    g_v);

    __half *p_x16, *p_ex16, *p_attn16, *p_h16, *p_f116;
    __half *p_wqkvT, *p_wsaoT, *p_wqT, *p_wkT, *p_wvT, *p_wcaoT, *p_w1T, *p_w2T;
    cudaGetSymbolAddress((void**)&p_x16,    g_x16);
    cudaGetSymbolAddress((void**)&p_ex16,   g_ex16);
    cudaGetSymbolAddress((void**)&p_attn16, g_attn16);
    cudaGetSymbolAddress((void**)&p_h16,    g_h16);
    cudaGetSymbolAddress((void**)&p_f116,   g_f116);
    cudaGetSymbolAddress((void**)&p_wqkvT,  g_wqkvT);
    cudaGetSymbolAddress((void**)&p_wsaoT,  g_wsaoT);
    cudaGetSymbolAddress((void**)&p_wqT,    g_wqT);
    cudaGetSymbolAddress((void**)&p_wkT,    g_wkT);
    cudaGetSymbolAddress((void**)&p_wvT,    g_wvT);
    cudaGetSymbolAddress((void**)&p_wcaoT,  g_wcaoT);
    cudaGetSymbolAddress((void**)&p_w1T,    g_w1T);
    cudaGetSymbolAddress((void**)&p_w2T,    g_w2T);

    const dim3 blk256(256);
    const dim3 t32(32, 32);
    const dim3 sblk(16, 16);
    const dim3 sgrd(32, 32, B_ * H_);
    const dim3 avblk(32, 32);
    const dim3 avgrd(32, 1, B_ * H_);

    // ---- weight prep (transpose + fp16) ----
    transpose_f16_kernel<<<dim3(3 * D_ / 32, D_ / 32), t32>>>(w_qkv, p_wqkvT, D_, 3 * D_);
    transpose_f16_kernel<<<dim3(D_ / 32, D_ / 32), t32>>>(w_sa_o, p_wsaoT, D_, D_);
    transpose_f16_kernel<<<dim3(D_ / 32, D_ / 32), t32>>>(w_q, p_wqT, D_, D_);
    transpose_f16_kernel<<<dim3(D_ / 32, D_ / 32), t32>>>(w_k, p_wkT, D_, D_);
    transpose_f16_kernel<<<dim3(D_ / 32, D_ / 32), t32>>>(w_v, p_wvT, D_, D_);
    transpose_f16_kernel<<<dim3(D_ / 32, D_ / 32), t32>>>(w_ca_o, p_wcaoT, D_, D_);
    transpose_f16_kernel<<<dim3(DFF_ / 32, D_ / 32), t32>>>(w1, p_w1T, D_, DFF_);
    transpose_f16_kernel<<<dim3(D_ / 32, DFF_ / 32), t32>>>(w2, p_w2T, DFF_, D_);
    f32_to_f16_kernel<<<4096, blk256>>>(x, p_x16, MROWS * D_);
    f32_to_f16_kernel<<<4096, blk256>>>(enc_x, p_ex16, B_ * E_ * D_);

    // ---- masked self-attention ----
    gemm_tc<<<dim3(3 * D_ / TN, MROWS / TM), 256>>>(
        p_x16, p_wqkvT, b_qkv, p_qkv, (__half*)0, MROWS, 3 * D_, D_, 0);
    scores_kernel<<<sgrd, sblk>>>(p_qkv, p_qkv, p_sc, 3 * D_, 3 * D_, 192, 192, 64, 1);
    softmax_kernel<<<B_ * H_ * S_, blk256>>>(p_sc);
    av_kernel<<<avgrd, avblk>>>(p_sc, p_qkv, p_attn, 3 * D_, 192, 128, 1);
    f32_to_f16_kernel<<<4096, blk256>>>(p_attn, p_attn16, MROWS * D_);
    gemm_tc<<<dim3(D_ / TN, MROWS / TM), 256>>>(
        p_attn16, p_wsaoT, b_sa_o, p_tmp, (__half*)0, MROWS, D_, D_, 0);
    add_ln_kernel<<<MROWS, blk256>>>(x, p_tmp, g1, be1, p_h1);
    f32_to_f16_kernel<<<4096, blk256>>>(p_h1, p_h16, MROWS * D_);

    // ---- cross-attention ----
    gemm_tc<<<dim3(D_ / TN, MROWS / TM), 256>>>(
        p_h16, p_wqT, b_q, p_q, (__half*)0, MROWS, D_, D_, 0);
    gemm_tc<<<dim3(D_ / TN, MROWS / TM), 256>>>(
        p_ex16, p_wkT, b_k, p_k, (__half*)0, B_ * E_, D_, D_, 0);
    gemm_tc<<<dim3(D_ / TN, MROWS / TM), 256>>>(
        p_ex16, p_wvT, b_v, p_v, (__half*)0, B_ * E_, D_, D_, 0);
    scores_kernel<<<sgrd, sblk>>>(p_q, p_k, p_sc, D_, D_, 64, 64, 0, 0);
    softmax_kernel<<<B_ * H_ * S_, blk256>>>(p_sc);
    av_kernel<<<avgrd, avblk>>>(p_sc, p_v, p_attn, D_, 64, 0, 0);
    f32_to_f16_kernel<<<4096, blk256>>>(p_attn, p_attn16, MROWS * D_);
    gemm_tc<<<dim3(D_ / TN, MROWS / TM), 256>>>(
        p_attn16, p_wcaoT, b_ca_o, p_tmp, (__half*)0, MROWS, D_, D_, 0);
    add_ln_kernel<<<MROWS, blk256>>>(p_h1, p_tmp, g2, be2, p_h2);
    f32_to_f16_kernel<<<4096, blk256>>>(p_h2, p_h16, MROWS * D_);

    // ---- FFN ----
    gemm_tc<<<dim3(DFF_ / TN, MROWS / TM), 256>>>(
        p_h16, p_w1T, b1, (float*)0, p_f116, MROWS, DFF_, D_, 1);
    gemm_tc<<<dim3(D_ / TN, MROWS / TM), 256>>>(
        p_f116, p_w2T, b2, p_tmp, (__half*)0, MROWS, D_, DFF_, 0);
    add_ln_kernel<<<MROWS, blk256>>>(p_h2, p_tmp, g3, be3, out);
}

// round 6
// speedup vs baseline: 9.3382x; 3.4687x over previous
#include <cuda_runtime.h>
#include <cuda_fp16.h>
#include <math.h>
#include <stdint.h>

// Problem constants
#define B_   4
#define S_   1024
#define E_   1024
#define D_   1024
#define H_   16
#define DH_  64
#define DFF_ 4096
#define MROWS (B_*S_)   // 4096

__device__ __forceinline__ uint32_t smem_u32(const void* p) {
    uint32_t a;
    asm("{ .reg .u64 t; cvta.to.shared.u64 t, %1; cvt.u32.u64 %0, t; }"
        : "=r"(a) : "l"(p));
    return a;
}

// ============================= scratch =====================================
__device__ float  g_tmp   [(size_t)MROWS * D_];
__device__ float  g_h1    [(size_t)MROWS * D_];
__device__ float  g_h2    [(size_t)MROWS * D_];

// fp16 buffers
__device__ __half g_x16   [(size_t)MROWS * D_];
__device__ __half g_ex16  [(size_t)B_ * E_ * D_];
__device__ __half g_qkv16 [(size_t)MROWS * 3 * D_];
__device__ __half g_attn16[(size_t)MROWS * D_];
__device__ __half g_h16   [(size_t)MROWS * D_];
__device__ __half g_q16   [(size_t)MROWS * D_];
__device__ __half g_k16   [(size_t)B_ * E_ * D_];
__device__ __half g_v16   [(size_t)B_ * E_ * D_];
__device__ __half g_f116  [(size_t)MROWS * DFF_];
// transposed fp16 weights [N,K]
__device__ __half g_wqkvT [(size_t)3 * D_ * D_];
__device__ __half g_wsaoT [(size_t)D_ * D_];
__device__ __half g_wqT   [(size_t)D_ * D_];
__device__ __half g_wkT   [(size_t)D_ * D_];
__device__ __half g_wvT   [(size_t)D_ * D_];
__device__ __half g_wcaoT [(size_t)D_ * D_];
__device__ __half g_w1T   [(size_t)D_ * DFF_];
__device__ __half g_w2T   [(size_t)DFF_ * D_];

// ======================== conversion kernels ===============================
__global__ __launch_bounds__(256)
void f32_to_f16_kernel(const float* __restrict__ in, __half* __restrict__ out, int n)
{
    int i = blockIdx.x * 256 + threadIdx.x;
    int stride = gridDim.x * 256;
    for (; i < n; i += stride) out[i] = __float2half(in[i]);
}

// W[K,N] fp32 -> Wt[N,K] fp16
__global__ __launch_bounds__(1024)
void transpose_f16_kernel(const float* __restrict__ W, __half* __restrict__ Wt,
                          int K, int N)
{
    __shared__ float t[32][33];
    int k = blockIdx.y * 32 + threadIdx.y;
    int n = blockIdx.x * 32 + threadIdx.x;
    t[threadIdx.y][threadIdx.x] = W[(size_t)k * N + n];
    __syncthreads();
    int nn = blockIdx.x * 32 + threadIdx.y;
    int kk = blockIdx.y * 32 + threadIdx.x;
    Wt[(size_t)nn * K + kk] = __float2half(t[threadIdx.x][threadIdx.y]);
}

// ========================= mma primitives ==================================
__device__ __forceinline__ void ldmx4(uint32_t* r, uint32_t addr) {
    asm volatile("ldmatrix.sync.aligned.m8n8.x4.shared.b16 {%0,%1,%2,%3}, [%4];"
                 : "=r"(r[0]), "=r"(r[1]), "=r"(r[2]), "=r"(r[3]) : "r"(addr));
}
__device__ __forceinline__ void ldmx4t(uint32_t* r, uint32_t addr) {
    asm volatile("ldmatrix.sync.aligned.m8n8.x4.trans.shared.b16 {%0,%1,%2,%3}, [%4];"
                 : "=r"(r[0]), "=r"(r[1]), "=r"(r[2]), "=r"(r[3]) : "r"(addr));
}
__device__ __forceinline__ void mma16816(float* c, const uint32_t* a, const uint32_t* b) {
    asm volatile("mma.sync.aligned.m16n8k16.row.col.f32.f16.f16.f32 "
                 "{%0,%1,%2,%3}, {%4,%5,%6,%7}, {%8,%9}, {%0,%1,%2,%3};"
                 : "+f"(c[0]), "+f"(c[1]), "+f"(c[2]), "+f"(c[3])
                 : "r"(a[0]), "r"(a[1]), "r"(a[2]), "r"(a[3]), "r"(b[0]), "r"(b[1]));
}
#define CP_ASYNC16(smem, gmem) \
    asm volatile("cp.async.cg.shared.global [%0], [%1], 16;" \
                 :: "r"(smem), "l"(gmem) : "memory")
#define CP_COMMIT() asm volatile("cp.async.commit_group;" ::: "memory")
#define CP_WAIT0()  asm volatile("cp.async.wait_group 0;" ::: "memory")

// ===================== mma.sync fp16 GEMM ==================================
#define TM 128
#define TN 128
#define KC 32
#define PAD 40

__global__ void __launch_bounds__(256, 2)
gemm_tc(const __half* __restrict__ A, const __half* __restrict__ Bt,
        const float* __restrict__ bias, float* __restrict__ outf,
        __half* __restrict__ outh, int M, int N, int K, int act)
{
    __shared__ __align__(16) __half sA[2][TM][PAD];
    __shared__ __align__(16) __half sB[2][TN][PAD];

    const int tid  = threadIdx.x;
    const int lane = tid & 31;
    const int wid  = tid >> 5;
    const int wm   = wid & 3;
    const int wn   = wid >> 2;
    const int m0 = blockIdx.y * TM;
    const int n0 = blockIdx.x * TN;

    float acc[2][8][4];
    #pragma unroll
    for (int i = 0; i < 2; i++)
        #pragma unroll
        for (int j = 0; j < 8; j++)
            #pragma unroll
            for (int q = 0; q < 4; q++) acc[i][j][q] = 0.f;

    const int r0c = tid >> 1;
    const int j0c = (tid & 1) * 2;
    const int nch = K / KC;

    {
        const __half* Ag = A  + (size_t)m0 * K;
        const __half* Bg = Bt + (size_t)n0 * K;
        #pragma unroll
        for (int j = 0; j < 2; j++) {
            CP_ASYNC16(smem_u32(&sA[0][r0c][(j0c + j) * 8]), Ag + (size_t)r0c * K + (j0c + j) * 8);
            CP_ASYNC16(smem_u32(&sB[0][r0c][(j0c + j) * 8]), Bg + (size_t)r0c * K + (j0c + j) * 8);
        }
        CP_COMMIT();
    }

    for (int c = 0; c < nch; c++) {
        CP_WAIT0();
        __syncthreads();

        if (c + 1 < nch) {
            const int st = (c + 1) & 1;
            const __half* Ag = A  + (size_t)m0 * K + (c + 1) * KC;
            const __half* Bg = Bt + (size_t)n0 * K + (c + 1) * KC;
            #pragma unroll
            for (int j = 0; j < 2; j++) {
                CP_ASYNC16(smem_u32(&sA[st][r0c][(j0c + j) * 8]), Ag + (size_t)r0c * K + (j0c + j) * 8);
                CP_ASYNC16(smem_u32(&sB[st][r0c][(j0c + j) * 8]), Bg + (size_t)r0c * K + (j0c + j) * 8);
            }
            CP_COMMIT();
        }

        const int st = c & 1;
        #pragma unroll
        for (int ks = 0; ks < KC; ks += 16) {
            uint32_t afr[2][4];
            #pragma unroll
            for (int mi = 0; mi < 2; mi++) {
                int r  = wm * 32 + mi * 16 + (lane & 15);
                int cc = ks + ((lane >> 4) << 3);
                ldmx4(afr[mi], smem_u32(&sA[st][r][cc]));
            }
            uint32_t bfr[4][4];
            #pragma unroll
            for (int nj = 0; nj < 4; nj++) {
                int r  = wn * 64 + nj * 16 + ((lane & 7) | ((lane & 16) >> 1));
                int cc = ks + (((lane >> 3) & 1) << 3);
                ldmx4(bfr[nj], smem_u32(&sB[st][r][cc]));
            }
            #pragma unroll
            for (int mi = 0; mi < 2; mi++)
                #pragma unroll
                for (int nj = 0; nj < 8; nj++)
                    mma16816(acc[mi][nj], afr[mi], &bfr[nj >> 1][(nj & 1) * 2]);
        }
        __syncthreads();
    }

    #pragma unroll
    for (int mi = 0; mi < 2; mi++) {
        #pragma unroll
        for (int rr = 0; rr < 2; rr++) {
            const int row = m0 + wm * 32 + mi * 16 + rr * 8 + (lane >> 2);
            #pragma unroll
            for (int nj = 0; nj < 8; nj++) {
                const int col = n0 + wn * 64 + nj * 8 + (lane & 3) * 2;
                float v0 = acc[mi][nj][rr * 2 + 0] + bias[col];
                float v1 = acc[mi][nj][rr * 2 + 1] + bias[col + 1];
                if (act) {
                    v0 = 0.5f * v0 * (1.0f + erff(v0 * 0.70710678118654752f));
                    v1 = 0.5f * v1 * (1.0f + erff(v1 * 0.70710678118654752f));
                }
                if (outf)
                    *(float2*)(outf + (size_t)row * N + col) = make_float2(v0, v1);
                if (outh)
                    *(__half2*)(outh + (size_t)row * N + col) = __floats2half2_rn(v0, v1);
            }
        }
    }
}

// ================= fused flash attention (fp16 mma) ========================
// One CTA: 64 query rows for one (b,h). 4 warps x 16 rows. K tiles of 64.
// Element access: X[(b*S + pos)*rs + h*hs + add + d]   (all in halfs)
__global__ void __launch_bounds__(128)
flash_kernel(const __half* __restrict__ Qp, const __half* __restrict__ Kp,
             const __half* __restrict__ Vp, __half* __restrict__ Op,
             int qrs, int krs, int qhs, int khs, int kadd, int vadd, int causal)
{
    __shared__ __align__(16) __half sQ[64][72];
    __shared__ __align__(16) __half sK[64][72];
    __shared__ __align__(16) __half sV[64][72];

    const int tid  = threadIdx.x;
    const int lane = tid & 31;
    const int warp = tid >> 5;
    const int bh = blockIdx.y;
    const int b  = bh >> 4;
    const int h  = bh & 15;
    const int q0 = blockIdx.x * 64;

    const __half* Qb = Qp + (size_t)(b * S_ + q0) * qrs + h * qhs;
    const __half* Kb = Kp + (size_t)(b * S_) * krs + h * khs + kadd;
    const __half* Vb = Vp + (size_t)(b * S_) * krs + h * khs + vadd;

    // load Q tile (scaled by 1/8)
    const __half2 sc8 = __float2half2_rn(0.125f);
    #pragma unroll
    for (int i = 0; i < 4; i++) {
        int ch = tid + i * 128;
        int r = ch >> 3, j = ch & 7;
        uint4 u = *(const uint4*)(Qb + (size_t)r * qrs + j * 8);
        __half2* hp = (__half2*)&u;
        #pragma unroll
        for (int q = 0; q < 4; q++) hp[q] = __hmul2(hp[q], sc8);
        *(uint4*)&sQ[r][j * 8] = u;
    }
    // load first K/V tile
    #pragma unroll
    for (int i = 0; i < 4; i++) {
        int ch = tid + i * 128;
        int r = ch >> 3, j = ch & 7;
        *(uint4*)&sK[r][j * 8] = *(const uint4*)(Kb + (size_t)r * krs + j * 8);
        *(uint4*)&sV[r][j * 8] = *(const uint4*)(Vb + (size_t)r * krs + j * 8);
    }
    __syncthreads();

    // preload Q fragments (stay in registers for all K tiles)
    uint32_t qf[4][4];
    #pragma unroll
    for (int ks = 0; ks < 4; ks++) {
        int r  = warp * 16 + (lane & 15);
        int cc = ks * 16 + ((lane >> 4) << 3);
        ldmx4(qf[ks], smem_u32(&sQ[r][cc]));
    }

    float m0 = -1e30f, m1 = -1e30f, l0 = 0.f, l1 = 0.f;
    float o[8][4];
    #pragma unroll
    for (int nj = 0; nj < 8; nj++)
        #pragma unroll
        for (int q = 0; q < 4; q++) o[nj][q] = 0.f;

    const int nkt = causal ? (blockIdx.x + 1) : (S_ / 64);

    for (int kt = 0; kt < nkt; kt++) {
        if (kt > 0) {
            __syncthreads();   // previous tile's reads finished
            #pragma unroll
            for (int i = 0; i < 4; i++) {
                int ch = tid + i * 128;
                int r = ch >> 3, j = ch & 7;
                *(uint4*)&sK[r][j * 8] = *(const uint4*)(Kb + (size_t)(kt * 64 + r) * krs + j * 8);
                *(uint4*)&sV[r][j * 8] = *(const uint4*)(Vb + (size_t)(kt * 64 + r) * krs + j * 8);
            }
            __syncthreads();
        }

        // S = Q @ K^T
        float s[8][4];
        #pragma unroll
        for (int nj = 0; nj < 8; nj++)
            #pragma unroll
            for (int q = 0; q < 4; q++) s[nj][q] = 0.f;

        #pragma unroll
        for (int ks = 0; ks < 4; ks++) {
            #pragma unroll
            for (int nj2 = 0; nj2 < 4; nj2++) {
                uint32_t bf[4];
                int r  = nj2 * 16 + ((lane & 7) | ((lane & 16) >> 1));
                int cc = ks * 16 + (((lane >> 3) & 1) << 3);
                ldmx4(bf, smem_u32(&sK[r][cc]));
                mma16816(s[2 * nj2],     qf[ks], &bf[0]);
                mma16816(s[2 * nj2 + 1], qf[ks], &bf[2]);
            }
        }

        // causal mask on diagonal tile
        if (causal && kt == (int)blockIdx.x) {
            int rl = warp * 16 + (lane >> 2);
            int c0 = (lane & 3) * 2;
            #pragma unroll
            for (int nj = 0; nj < 8; nj++) {
                int k0l = nj * 8 + c0;
                if (k0l     > rl)     s[nj][0] = -1e30f;
                if (k0l + 1 > rl)     s[nj][1] = -1e30f;
                if (k0l     > rl + 8) s[nj][2] = -1e30f;
                if (k0l + 1 > rl + 8) s[nj][3] = -1e30f;
            }
        }

        // online softmax
        float mx0 = -1e30f, mx1 = -1e30f;
        #pragma unroll
        for (int nj = 0; nj < 8; nj++) {
            mx0 = fmaxf(mx0, fmaxf(s[nj][0], s[nj][1]));
            mx1 = fmaxf(mx1, fmaxf(s[nj][2], s[nj][3]));
        }
        mx0 = fmaxf(mx0, __shfl_xor_sync(~0u, mx0, 1));
        mx0 = fmaxf(mx0, __shfl_xor_sync(~0u, mx0, 2));
        mx1 = fmaxf(mx1, __shfl_xor_sync(~0u, mx1, 1));
        mx1 = fmaxf(mx1, __shfl_xor_sync(~0u, mx1, 2));

        float nm0 = fmaxf(m0, mx0), nm1 = fmaxf(m1, mx1);
        float sc0 = __expf(m0 - nm0), sc1 = __expf(m1 - nm1);
        m0 = nm0; m1 = nm1;
        l0 *= sc0; l1 *= sc1;
        #pragma unroll
        for (int nj = 0; nj < 8; nj++) {
            o[nj][0] *= sc0; o[nj][1] *= sc0;
            o[nj][2] *= sc1; o[nj][3] *= sc1;
        }

        uint32_t pk[8][2];
        float rs0 = 0.f, rs1 = 0.f;
        #pragma unroll
        for (int nj = 0; nj < 8; nj++) {
            float p0 = __expf(s[nj][0] - m0), p1 = __expf(s[nj][1] - m0);
            float p2 = __expf(s[nj][2] - m1), p3 = __expf(s[nj][3] - m1);
            rs0 += p0 + p1; rs1 += p2 + p3;
            __half2 hA = __floats2half2_rn(p0, p1);
            __half2 hB = __floats2half2_rn(p2, p3);
            pk[nj][0] = *(uint32_t*)&hA;
            pk[nj][1] = *(uint32_t*)&hB;
        }
        l0 += rs0; l1 += rs1;

        // O += P @ V   (V fragments via ldmatrix.trans on row-major sV)
        #pragma unroll
        for (int t = 0; t < 4; t++) {
            uint32_t a[4] = { pk[2 * t][0], pk[2 * t][1], pk[2 * t + 1][0], pk[2 * t + 1][1] };
            #pragma unroll
            for (int nj2 = 0; nj2 < 4; nj2++) {
                uint32_t bf[4];
                int r  = t * 16 + (lane & 15);
                int cc = nj2 * 16 + ((lane >> 4) << 3);
                ldmx4t(bf, smem_u32(&sV[r][cc]));
                mma16816(o[2 * nj2],     a, &bf[0]);
                mma16816(o[2 * nj2 + 1], a, &bf[2]);
            }
        }
    }

    // finalize: reduce l across quad, divide, write fp16
    l0 += __shfl_xor_sync(~0u, l0, 1);
    l0 += __shfl_xor_sync(~0u, l0, 2);
    l1 += __shfl_xor_sync(~0u, l1, 1);
    l1 += __shfl_xor_sync(~0u, l1, 2);
    float inv0 = 1.f / l0, inv1 = 1.f / l1;

    const int row0 = q0 + warp * 16 + (lane >> 2);
    #pragma unroll
    for (int nj = 0; nj < 8; nj++) {
        int col = h * 64 + nj * 8 + (lane & 3) * 2;
        *(__half2*)(Op + (size_t)(b * S_ + row0) * D_ + col) =
            __floats2half2_rn(o[nj][0] * inv0, o[nj][1] * inv0);
        *(__half2*)(Op + (size_t)(b * S_ + row0 + 8) * D_ + col) =
            __floats2half2_rn(o[nj][2] * inv1, o[nj][3] * inv1);
    }
}

// ---------------- fused residual-add + LayerNorm (fp32 + optional fp16) ----
__global__ __launch_bounds__(256)
void add_ln_kernel(const float* __restrict__ resid, const float* __restrict__ y,
                   const float* __restrict__ g, const float* __restrict__ be,
                   float* __restrict__ out, __half* __restrict__ out16)
{
    const size_t base = (size_t)blockIdx.x * 1024;
    const int t = threadIdx.x;
    __shared__ float red[8];

    float v[4];
    float s = 0;
    #pragma unroll
    for (int i = 0; i < 4; i++) {
        v[i] = resid[base + t + i * 256] + y[base + t + i * 256];
        s += v[i];
    }
    #pragma unroll
    for (int o = 16; o; o >>= 1) s += __shfl_xor_sync(~0u, s, o);
    if ((t & 31) == 0) red[t >> 5] = s;
    __syncthreads();
    float tot = 0;
    #pragma unroll
    for (int i = 0; i < 8; i++) tot += red[i];
    float mean = tot * (1.0f / 1024.0f);
    __syncthreads();

    float vs = 0;
    #pragma unroll
    for (int i = 0; i < 4; i++) { float d = v[i] - mean; vs += d * d; }
    #pragma unroll
    for (int o = 16; o; o >>= 1) vs += __shfl_xor_sync(~0u, vs, o);
    if ((t & 31) == 0) red[t >> 5] = vs;
    __syncthreads();
    tot = 0;
    #pragma unroll
    for (int i = 0; i < 8; i++) tot += red[i];
    float inv = rsqrtf(tot * (1.0f / 1024.0f) + 1e-5f);

    #pragma unroll
    for (int i = 0; i < 4; i++) {
        int c = t + i * 256;
        float r = g[c] * (v[i] - mean) * inv + be[c];
        out[base + c] = r;
        if (out16) out16[base + c] = __float2half(r);
    }
}

// ================================ launch ===================================
extern "C" void kernel_launch(void* const* d_in, const int* in_sizes, int n_in,
                              void* d_out, int out_size)
{
    const float* x      = (const float*)d_in[0];
    const float* enc_x  = (const float*)d_in[1];
    const float* w_qkv  = (const float*)d_in[2];
    const float* b_qkv  = (const float*)d_in[3];
    const float* w_sa_o = (const float*)d_in[4];
    const float* b_sa_o = (const float*)d_in[5];
    const float* w_q    = (const float*)d_in[6];
    const float* b_q    = (const float*)d_in[7];
    const float* w_k    = (const float*)d_in[8];
    const float* b_k    = (const float*)d_in[9];
    const float* w_v    = (const float*)d_in[10];
    const float* b_v    = (const float*)d_in[11];
    const float* w_ca_o = (const float*)d_in[12];
    const float* b_ca_o = (const float*)d_in[13];
    const float* w1     = (const float*)d_in[14];
    const float* b1     = (const float*)d_in[15];
    const float* w2     = (const float*)d_in[16];
    const float* b2     = (const float*)d_in[17];
    const float* g1     = (const float*)d_in[18];
    const float* be1    = (const float*)d_in[19];
    const float* g2     = (const float*)d_in[20];
    const float* be2    = (const float*)d_in[21];
    const float* g3     = (const float*)d_in[22];
    const float* be3    = (const float*)d_in[23];
    float* out = (float*)d_out;

    float *p_tmp, *p_h1, *p_h2;
    cudaGetSymbolAddress((void**)&p_tmp,  g_tmp);
    cudaGetSymbolAddress((void**)&p_h1,   g_h1);
    cudaGetSymbolAddress((void**)&p_h2,   g_h2);

    __half *p_x16, *p_ex16, *p_qkv16, *p_attn16, *p_h16, *p_q16, *p_k16, *p_v16, *p_f116;
    __half *p_wqkvT, *p_wsaoT, *p_wqT, *p_wkT, *p_wvT, *p_wcaoT, *p_w1T, *p_w2T;
    cudaGetSymbolAddress((void**)&p_x16,    g_x16);
    cudaGetSymbolAddress((void**)&p_ex16,   g_ex16);
    cudaGetSymbolAddress((void**)&p_qkv16,  g_qkv16);
    cudaGetSymbolAddress((void**)&p_attn16, g_attn16);
    cudaGetSymbolAddress((void**)&p_h16,    g_h16);
    cudaGetSymbolAddress((void**)&p_q16,    g_q16);
    cudaGetSymbolAddress((void**)&p_k16,    g_k16);
    cudaGetSymbolAddress((void**)&p_v16,    g_v16);
    cudaGetSymbolAddress((void**)&p_f116,   g_f116);
    cudaGetSymbolAddress((void**)&p_wqkvT,  g_wqkvT);
    cudaGetSymbolAddress((void**)&p_wsaoT,  g_wsaoT);
    cudaGetSymbolAddress((void**)&p_wqT,    g_wqT);
    cudaGetSymbolAddress((void**)&p_wkT,    g_wkT);
    cudaGetSymbolAddress((void**)&p_wvT,    g_wvT);
    cudaGetSymbolAddress((void**)&p_wcaoT,  g_wcaoT);
    cudaGetSymbolAddress((void**)&p_w1T,    g_w1T);
    cudaGetSymbolAddress((void**)&p_w2T,    g_w2T);

    const dim3 blk256(256);
    const dim3 t32(32, 32);
    const dim3 fgrd(S_ / 64, B_ * H_);

    // ---- weight prep (transpose + fp16) ----
    transpose_f16_kernel<<<dim3(3 * D_ / 32, D_ / 32), t32>>>(w_qkv, p_wqkvT, D_, 3 * D_);
    transpose_f16_kernel<<<dim3(D_ / 32, D_ / 32), t32>>>(w_sa_o, p_wsaoT, D_, D_);
    transpose_f16_kernel<<<dim3(D_ / 32, D_ / 32), t32>>>(w_q, p_wqT, D_, D_);
    transpose_f16_kernel<<<dim3(D_ / 32, D_ / 32), t32>>>(w_k, p_wkT, D_, D_);
    transpose_f16_kernel<<<dim3(D_ / 32, D_ / 32), t32>>>(w_v, p_wvT, D_, D_);
    transpose_f16_kernel<<<dim3(D_ / 32, D_ / 32), t32>>>(w_ca_o, p_wcaoT, D_, D_);
    transpose_f16_kernel<<<dim3(DFF_ / 32, D_ / 32), t32>>>(w1, p_w1T, D_, DFF_);
    transpose_f16_kernel<<<dim3(D_ / 32, DFF_ / 32), t32>>>(w2, p_w2T, DFF_, D_);
    f32_to_f16_kernel<<<4096, blk256>>>(x, p_x16, MROWS * D_);
    f32_to_f16_kernel<<<4096, blk256>>>(enc_x, p_ex16, B_ * E_ * D_);

    // ---- masked self-attention ----
    gemm_tc<<<dim3(3 * D_ / TN, MROWS / TM), 256>>>(
        p_x16, p_wqkvT, b_qkv, (float*)0, p_qkv16, MROWS, 3 * D_, D_, 0);
    flash_kernel<<<fgrd, 128>>>(p_qkv16, p_qkv16, p_qkv16, p_attn16,
                                3 * D_, 3 * D_, 192, 192, 64, 128, 1);
    gemm_tc<<<dim3(D_ / TN, MROWS / TM), 256>>>(
        p_attn16, p_wsaoT, b_sa_o, p_tmp, (__half*)0, MROWS, D_, D_, 0);
    add_ln_kernel<<<MROWS, blk256>>>(x, p_tmp, g1, be1, p_h1, p_h16);

    // ---- cross-attention ----
    gemm_tc<<<dim3(D_ / TN, MROWS / TM), 256>>>(
        p_h16, p_wqT, b_q, (float*)0, p_q16, MROWS, D_, D_, 0);
    gemm_tc<<<dim3(D_ / TN, MROWS / TM), 256>>>(
        p_ex16, p_wkT, b_k, (float*)0, p_k16, B_ * E_, D_, D_, 0);
    gemm_tc<<<dim3(D_ / TN, MROWS / TM), 256>>>(
        p_ex16, p_wvT, b_v, (float*)0, p_v16, B_ * E_, D_, D_, 0);
    flash_kernel<<<fgrd, 128>>>(p_q16, p_k16, p_v16, p_attn16,
                                D_, D_, 64, 64, 0, 0, 0);
    gemm_tc<<<dim3(D_ / TN, MROWS / TM), 256>>>(
        p_attn16, p_wcaoT, b_ca_o, p_tmp, (__half*)0, MROWS, D_, D_, 0);
    add_ln_kernel<<<MROWS, blk256>>>(p_h1, p_tmp, g2, be2, p_h2, p_h16);

    // ---- FFN ----
    gemm_tc<<<dim3(DFF_ / TN, MROWS / TM), 256>>>(
        p_h16, p_w1T, b1, (float*)0, p_f116, MROWS, DFF_, D_, 1);
    gemm_tc<<<dim3(D_ / TN, MROWS / TM), 256>>>(
        p_f116, p_w2T, b2, p_tmp, (__half*)0, MROWS, D_, DFF_, 0);
    add_ln_kernel<<<MROWS, blk256>>>(p_h2, p_tmp, g3, be3, out, (__half*)0);
}

// round 8
// speedup vs baseline: 9.4988x; 1.0172x over previous
#include <cuda_runtime.h>
#include <cuda_fp16.h>
#include <math.h>
#include <stdint.h>

// Problem constants
#define B_   4
#define S_   1024
#define E_   1024
#define D_   1024
#define H_   16
#define DH_  64
#define DFF_ 4096
#define MROWS (B_*S_)   // 4096

__device__ __forceinline__ uint32_t smem_u32(const void* p) {
    uint32_t a;
    asm("{ .reg .u64 t; cvta.to.shared.u64 t, %1; cvt.u32.u64 %0, t; }"
        : "=r"(a) : "l"(p));
    return a;
}

// ============================= scratch =====================================
__device__ float  g_tmp   [(size_t)MROWS * D_];
__device__ float  g_h1    [(size_t)MROWS * D_];
__device__ float  g_h2    [(size_t)MROWS * D_];

// fp16 buffers
__device__ __half g_x16   [(size_t)MROWS * D_];
__device__ __half g_ex16  [(size_t)B_ * E_ * D_];
__device__ __half g_qkv16 [(size_t)MROWS * 3 * D_];
__device__ __half g_attn16[(size_t)MROWS * D_];
__device__ __half g_h16   [(size_t)MROWS * D_];
__device__ __half g_q16   [(size_t)MROWS * D_];
__device__ __half g_k16   [(size_t)B_ * E_ * D_];
__device__ __half g_v16   [(size_t)B_ * E_ * D_];
__device__ __half g_f116  [(size_t)MROWS * DFF_];
// transposed fp16 weights [N,K]
__device__ __half g_wqkvT [(size_t)3 * D_ * D_];
__device__ __half g_wsaoT [(size_t)D_ * D_];
__device__ __half g_wqT   [(size_t)D_ * D_];
__device__ __half g_wkT   [(size_t)D_ * D_];
__device__ __half g_wvT   [(size_t)D_ * D_];
__device__ __half g_wcaoT [(size_t)D_ * D_];
__device__ __half g_w1T   [(size_t)D_ * DFF_];
__device__ __half g_w2T   [(size_t)DFF_ * D_];

// ======================== conversion kernels ===============================
__global__ __launch_bounds__(256)
void f32_to_f16_kernel(const float* __restrict__ in, __half* __restrict__ out, int n)
{
    int i = blockIdx.x * 256 + threadIdx.x;
    int stride = gridDim.x * 256;
    for (; i < n; i += stride) out[i] = __float2half(in[i]);
}

// W[K,N] fp32 -> Wt[N,K] fp16
__global__ __launch_bounds__(1024)
void transpose_f16_kernel(const float* __restrict__ W, __half* __restrict__ Wt,
                          int K, int N)
{
    __shared__ float t[32][33];
    int k = blockIdx.y * 32 + threadIdx.y;
    int n = blockIdx.x * 32 + threadIdx.x;
    t[threadIdx.y][threadIdx.x] = W[(size_t)k * N + n];
    __syncthreads();
    int nn = blockIdx.x * 32 + threadIdx.y;
    int kk = blockIdx.y * 32 + threadIdx.x;
    Wt[(size_t)nn * K + kk] = __float2half(t[threadIdx.x][threadIdx.y]);
}

// ========================= mma primitives ==================================
__device__ __forceinline__ void ldmx4(uint32_t* r, uint32_t addr) {
    asm volatile("ldmatrix.sync.aligned.m8n8.x4.shared.b16 {%0,%1,%2,%3}, [%4];"
                 : "=r"(r[0]), "=r"(r[1]), "=r"(r[2]), "=r"(r[3]) : "r"(addr));
}
__device__ __forceinline__ void ldmx4t(uint32_t* r, uint32_t addr) {
    asm volatile("ldmatrix.sync.aligned.m8n8.x4.trans.shared.b16 {%0,%1,%2,%3}, [%4];"
                 : "=r"(r[0]), "=r"(r[1]), "=r"(r[2]), "=r"(r[3]) : "r"(addr));
}
__device__ __forceinline__ void mma16816(float* c, const uint32_t* a, const uint32_t* b) {
    asm volatile("mma.sync.aligned.m16n8k16.row.col.f32.f16.f16.f32 "
                 "{%0,%1,%2,%3}, {%4,%5,%6,%7}, {%8,%9}, {%0,%1,%2,%3};"
                 : "+f"(c[0]), "+f"(c[1]), "+f"(c[2]), "+f"(c[3])
                 : "r"(a[0]), "r"(a[1]), "r"(a[2]), "r"(a[3]), "r"(b[0]), "r"(b[1]));
}
#define CP_ASYNC16(smem, gmem) \
    asm volatile("cp.async.cg.shared.global [%0], [%1], 16;" \
                 :: "r"(smem), "l"(gmem) : "memory")
#define CP_COMMIT() asm volatile("cp.async.commit_group;" ::: "memory")
#define CP_WAIT0()  asm volatile("cp.async.wait_group 0;" ::: "memory")
#define CP_WAIT1()  asm volatile("cp.async.wait_group 1;" ::: "memory")

// ===================== mma.sync fp16 GEMM ==================================
// C[M,N] = A[M,K] (fp16 row-major) @ Bt[N,K]^T (fp16) + bias ; opt GELU.
// CTA tile 128x128x32, 8 warps (4m x 2n). 3-stage cp.async ring.
#define TM 128
#define TN 128
#define KC 32
#define PAD 40
#define GEMM_SMEM (3 * (TM + TN) * PAD * 2)   // 61440 bytes

__global__ void __launch_bounds__(256, 2)
gemm_tc(const __half* __restrict__ A, const __half* __restrict__ Bt,
        const float* __restrict__ bias, float* __restrict__ outf,
        __half* __restrict__ outh, int M, int N, int K, int act)
{
    extern __shared__ char dynsm[];
    const uint32_t sbase = smem_u32(dynsm);
    // layout: 3 stages of A (TM*PAD halfs), then 3 stages of B
    #define SA_ADDR(st, r, c) (sbase + (uint32_t)(st) * (TM * PAD * 2) + (uint32_t)((r) * PAD + (c)) * 2)
    #define SB_ADDR(st, r, c) (sbase + 3u * TM * PAD * 2 + (uint32_t)(st) * (TN * PAD * 2) + (uint32_t)((r) * PAD + (c)) * 2)

    const int tid  = threadIdx.x;
    const int lane = tid & 31;
    const int wid  = tid >> 5;
    const int wm   = wid & 3;
    const int wn   = wid >> 2;
    const int m0 = blockIdx.y * TM;
    const int n0 = blockIdx.x * TN;

    float acc[2][8][4];
    #pragma unroll
    for (int i = 0; i < 2; i++)
        #pragma unroll
        for (int j = 0; j < 8; j++)
            #pragma unroll
            for (int q = 0; q < 4; q++) acc[i][j][q] = 0.f;

    const int r0c = tid >> 1;              // row 0..127
    const int j0c = (tid & 1) * 2;         // first of two 16B chunks
    const int nch = K / KC;                // >= 32

    // prologue: stage 0 and 1
    #pragma unroll
    for (int p = 0; p < 2; p++) {
        const __half* Ag = A  + (size_t)m0 * K + p * KC;
        const __half* Bg = Bt + (size_t)n0 * K + p * KC;
        #pragma unroll
        for (int j = 0; j < 2; j++) {
            CP_ASYNC16(SA_ADDR(p, r0c, (j0c + j) * 8), Ag + (size_t)r0c * K + (j0c + j) * 8);
            CP_ASYNC16(SB_ADDR(p, r0c, (j0c + j) * 8), Bg + (size_t)r0c * K + (j0c + j) * 8);
        }
        CP_COMMIT();
    }

    int st = 0, stw = 2;   // read stage, write stage (mod-3 counters)
    for (int c = 0; c < nch; c++) {
        CP_WAIT1();             // stage c complete (stage c+1 may be pending)
        __syncthreads();

        if (c + 2 < nch) {
            const __half* Ag = A  + (size_t)m0 * K + (c + 2) * KC;
            const __half* Bg = Bt + (size_t)n0 * K + (c + 2) * KC;
            #pragma unroll
            for (int j = 0; j < 2; j++) {
                CP_ASYNC16(SA_ADDR(stw, r0c, (j0c + j) * 8), Ag + (size_t)r0c * K + (j0c + j) * 8);
                CP_ASYNC16(SB_ADDR(stw, r0c, (j0c + j) * 8), Bg + (size_t)r0c * K + (j0c + j) * 8);
            }
            CP_COMMIT();
        }

        #pragma unroll
        for (int ks = 0; ks < KC; ks += 16) {
            uint32_t afr[2][4];
            #pragma unroll
            for (int mi = 0; mi < 2; mi++) {
                int r  = wm * 32 + mi * 16 + (lane & 15);
                int cc = ks + ((lane >> 4) << 3);
                ldmx4(afr[mi], SA_ADDR(st, r, cc));
            }
            uint32_t bfr[4][4];
            #pragma unroll
            for (int nj = 0; nj < 4; nj++) {
                int r  = wn * 64 + nj * 16 + ((lane & 7) | ((lane & 16) >> 1));
                int cc = ks + (((lane >> 3) & 1) << 3);
                ldmx4(bfr[nj], SB_ADDR(st, r, cc));
            }
            #pragma unroll
            for (int mi = 0; mi < 2; mi++)
                #pragma unroll
                for (int nj = 0; nj < 8; nj++)
                    mma16816(acc[mi][nj], afr[mi], &bfr[nj >> 1][(nj & 1) * 2]);
        }

        st  = (st  == 2) ? 0 : st  + 1;
        stw = (stw == 2) ? 0 : stw + 1;
    }

    #pragma unroll
    for (int mi = 0; mi < 2; mi++) {
        #pragma unroll
        for (int rr = 0; rr < 2; rr++) {
            const int row = m0 + wm * 32 + mi * 16 + rr * 8 + (lane >> 2);
            #pragma unroll
            for (int nj = 0; nj < 8; nj++) {
                const int col = n0 + wn * 64 + nj * 8 + (lane & 3) * 2;
                float v0 = acc[mi][nj][rr * 2 + 0] + bias[col];
                float v1 = acc[mi][nj][rr * 2 + 1] + bias[col + 1];
                if (act) {
                    v0 = 0.5f * v0 * (1.0f + erff(v0 * 0.70710678118654752f));
                    v1 = 0.5f * v1 * (1.0f + erff(v1 * 0.70710678118654752f));
                }
                if (outf)
                    *(float2*)(outf + (size_t)row * N + col) = make_float2(v0, v1);
                if (outh)
                    *(__half2*)(outh + (size_t)row * N + col) = __floats2half2_rn(v0, v1);
            }
        }
    }
    #undef SA_ADDR
    #undef SB_ADDR
}

// ================= fused flash attention (fp16 mma) ========================
// One CTA: 64 query rows for one (b,h). 4 warps x 16 rows. K tiles of 64.
// K/V double-buffered via cp.async.
__global__ void __launch_bounds__(128)
flash_kernel(const __half* __restrict__ Qp, const __half* __restrict__ Kp,
             const __half* __restrict__ Vp, __half* __restrict__ Op,
             int qrs, int krs, int qhs, int khs, int kadd, int vadd, int causal)
{
    __shared__ __align__(16) __half sQ[64][72];
    __shared__ __align__(16) __half sK[2][64][72];
    __shared__ __align__(16) __half sV[2][64][72];

    const int tid  = threadIdx.x;
    const int lane = tid & 31;
    const int warp = tid >> 5;
    const int bh = blockIdx.y;
    const int b  = bh >> 4;
    const int h  = bh & 15;
    const int q0 = blockIdx.x * 64;

    const __half* Qb = Qp + (size_t)(b * S_ + q0) * qrs + h * qhs;
    const __half* Kb = Kp + (size_t)(b * S_) * krs + h * khs + kadd;
    const __half* Vb = Vp + (size_t)(b * S_) * krs + h * khs + vadd;

    // load Q tile (scaled by 1/8) — plain loads (needs the multiply)
    const __half2 sc8 = __float2half2_rn(0.125f);
    #pragma unroll
    for (int i = 0; i < 4; i++) {
        int ch = tid + i * 128;
        int r = ch >> 3, j = ch & 7;
        uint4 u = *(const uint4*)(Qb + (size_t)r * qrs + j * 8);
        __half2* hp = (__half2*)&u;
        #pragma unroll
        for (int q = 0; q < 4; q++) hp[q] = __hmul2(hp[q], sc8);
        *(uint4*)&sQ[r][j * 8] = u;
    }
    // async-load first K/V tile into buf 0
    #pragma unroll
    for (int i = 0; i < 4; i++) {
        int ch = tid + i * 128;
        int r = ch >> 3, j = ch & 7;
        CP_ASYNC16(smem_u32(&sK[0][r][j * 8]), Kb + (size_t)r * krs + j * 8);
        CP_ASYNC16(smem_u32(&sV[0][r][j * 8]), Vb + (size_t)r * krs + j * 8);
    }
    CP_COMMIT();

    uint32_t qf[4][4];
    float m0 = -1e30f, m1 = -1e30f, l0 = 0.f, l1 = 0.f;
    float o[8][4];
    #pragma unroll
    for (int nj = 0; nj < 8; nj++)
        #pragma unroll
        for (int q = 0; q < 4; q++) o[nj][q] = 0.f;

    const int nkt = causal ? (blockIdx.x + 1) : (S_ / 64);

    for (int kt = 0; kt < nkt; kt++) {
        CP_WAIT0();
        __syncthreads();

        if (kt == 0) {
            // preload Q fragments (registers for the whole loop)
            #pragma unroll
            for (int ks = 0; ks < 4; ks++) {
                int r  = warp * 16 + (lane & 15);
                int cc = ks * 16 + ((lane >> 4) << 3);
                ldmx4(qf[ks], smem_u32(&sQ[r][cc]));
            }
        }
        // prefetch next K/V tile
        if (kt + 1 < nkt) {
            const int nb = (kt + 1) & 1;
            #pragma unroll
            for (int i = 0; i < 4; i++) {
                int ch = tid + i * 128;
                int r = ch >> 3, j = ch & 7;
                CP_ASYNC16(smem_u32(&sK[nb][r][j * 8]), Kb + (size_t)((kt + 1) * 64 + r) * krs + j * 8);
                CP_ASYNC16(smem_u32(&sV[nb][r][j * 8]), Vb + (size_t)((kt + 1) * 64 + r) * krs + j * 8);
            }
            CP_COMMIT();
        }
        const int cb = kt & 1;

        // S = Q @ K^T
        float s[8][4];
        #pragma unroll
        for (int nj = 0; nj < 8; nj++)
            #pragma unroll
            for (int q = 0; q < 4; q++) s[nj][q] = 0.f;

        #pragma unroll
        for (int ks = 0; ks < 4; ks++) {
            #pragma unroll
            for (int nj2 = 0; nj2 < 4; nj2++) {
                uint32_t bf[4];
                int r  = nj2 * 16 + ((lane & 7) | ((lane & 16) >> 1));
                int cc = ks * 16 + (((lane >> 3) & 1) << 3);
                ldmx4(bf, smem_u32(&sK[cb][r][cc]));
                mma16816(s[2 * nj2],     qf[ks], &bf[0]);
                mma16816(s[2 * nj2 + 1], qf[ks], &bf[2]);
            }
        }

        // causal mask on diagonal tile
        if (causal && kt == (int)blockIdx.x) {
            int rl = warp * 16 + (lane >> 2);
            int c0 = (lane & 3) * 2;
            #pragma unroll
            for (int nj = 0; nj < 8; nj++) {
                int k0l = nj * 8 + c0;
                if (k0l     > rl)     s[nj][0] = -1e30f;
                if (k0l + 1 > rl)     s[nj][1] = -1e30f;
                if (k0l     > rl + 8) s[nj][2] = -1e30f;
                if (k0l + 1 > rl + 8) s[nj][3] = -1e30f;
            }
        }

        // online softmax
        float mx0 = -1e30f, mx1 = -1e30f;
        #pragma unroll
        for (int nj = 0; nj < 8; nj++) {
            mx0 = fmaxf(mx0, fmaxf(s[nj][0], s[nj][1]));
            mx1 = fmaxf(mx1, fmaxf(s[nj][2], s[nj][3]));
        }
        mx0 = fmaxf(mx0, __shfl_xor_sync(~0u, mx0, 1));
        mx0 = fmaxf(mx0, __shfl_xor_sync(~0u, mx0, 2));
        mx1 = fmaxf(mx1, __shfl_xor_sync(~0u, mx1, 1));
        mx1 = fmaxf(mx1, __shfl_xor_sync(~0u, mx1, 2));

        float nm0 = fmaxf(m0, mx0), nm1 = fmaxf(m1, mx1);
        float sc0 = __expf(m0 - nm0), sc1 = __expf(m1 - nm1);
        m0 = nm0; m1 = nm1;
        l0 *= sc0; l1 *= sc1;
        #pragma unroll
        for (int nj = 0; nj < 8; nj++) {
            o[nj][0] *= sc0; o[nj][1] *= sc0;
            o[nj][2] *= sc1; o[nj][3] *= sc1;
        }

        uint32_t pk[8][2];
        float rs0 = 0.f, rs1 = 0.f;
        #pragma unroll
        for (int nj = 0; nj < 8; nj++) {
            float p0 = __expf(s[nj][0] - m0), p1 = __expf(s[nj][1] - m0);
            float p2 = __expf(s[nj][2] - m1), p3 = __expf(s[nj][3] - m1);
            rs0 += p0 + p1; rs1 += p2 + p3;
            __half2 hA = __floats2half2_rn(p0, p1);
            __half2 hB = __floats2half2_rn(p2, p3);
            pk[nj][0] = *(uint32_t*)&hA;
            pk[nj][1] = *(uint32_t*)&hB;
        }
        l0 += rs0; l1 += rs1;

        // O += P @ V   (V fragments via ldmatrix.trans on row-major sV)
        #pragma unroll
        for (int t = 0; t < 4; t++) {
            uint32_t a[4] = { pk[2 * t][0], pk[2 * t][1], pk[2 * t + 1][0], pk[2 * t + 1][1] };
            #pragma unroll
            for (int nj2 = 0; nj2 < 4; nj2++) {
                uint32_t bf[4];
                int r  = t * 16 + (lane & 15);
                int cc = nj2 * 16 + ((lane >> 4) << 3);
                ldmx4t(bf, smem_u32(&sV[cb][r][cc]));
                mma16816(o[2 * nj2],     a, &bf[0]);
                mma16816(o[2 * nj2 + 1], a, &bf[2]);
            }
        }
    }

    // finalize
    l0 += __shfl_xor_sync(~0u, l0, 1);
    l0 += __shfl_xor_sync(~0u, l0, 2);
    l1 += __shfl_xor_sync(~0u, l1, 1);
    l1 += __shfl_xor_sync(~0u, l1, 2);
    float inv0 = 1.f / l0, inv1 = 1.f / l1;

    const int row0 = q0 + warp * 16 + (lane >> 2);
    #pragma unroll
    for (int nj = 0; nj < 8; nj++) {
        int col = h * 64 + nj * 8 + (lane & 3) * 2;
        *(__half2*)(Op + (size_t)(b * S_ + row0) * D_ + col) =
            __floats2half2_rn(o[nj][0] * inv0, o[nj][1] * inv0);
        *(__half2*)(Op + (size_t)(b * S_ + row0 + 8) * D_ + col) =
            __floats2half2_rn(o[nj][2] * inv1, o[nj][3] * inv1);
    }
}

// ---------------- fused residual-add + LayerNorm (fp32 + optional fp16) ----
__global__ __launch_bounds__(256)
void add_ln_kernel(const float* __restrict__ resid, const float* __restrict__ y,
                   const float* __restrict__ g, const float* __restrict__ be,
                   float* __restrict__ out, __half* __restrict__ out16)
{
    const size_t base = (size_t)blockIdx.x * 1024;
    const int t = threadIdx.x;
    __shared__ float red[8];

    float v[4];
    float s = 0;
    #pragma unroll
    for (int i = 0; i < 4; i++) {
        v[i] = resid[base + t + i * 256] + y[base + t + i * 256];
        s += v[i];
    }
    #pragma unroll
    for (int o = 16; o; o >>= 1) s += __shfl_xor_sync(~0u, s, o);
    if ((t & 31) == 0) red[t >> 5] = s;
    __syncthreads();
    float tot = 0;
    #pragma unroll
    for (int i = 0; i < 8; i++) tot += red[i];
    float mean = tot * (1.0f / 1024.0f);
    __syncthreads();

    float vs = 0;
    #pragma unroll
    for (int i = 0; i < 4; i++) { float d = v[i] - mean; vs += d * d; }
    #pragma unroll
    for (int o = 16; o; o >>= 1) vs += __shfl_xor_sync(~0u, vs, o);
    if ((t & 31) == 0) red[t >> 5] = vs;
    __syncthreads();
    tot = 0;
    #pragma unroll
    for (int i = 0; i < 8; i++) tot += red[i];
    float inv = rsqrtf(tot * (1.0f / 1024.0f) + 1e-5f);

    #pragma unroll
    for (int i = 0; i < 4; i++) {
        int c = t + i * 256;
        float r = g[c] * (v[i] - mean) * inv + be[c];
        out[base + c] = r;
        if (out16) out16[base + c] = __float2half(r);
    }
}

// ================================ launch ===================================
extern "C" void kernel_launch(void* const* d_in, const int* in_sizes, int n_in,
                              void* d_out, int out_size)
{
    const float* x      = (const float*)d_in[0];
    const float* enc_x  = (const float*)d_in[1];
    const float* w_qkv  = (const float*)d_in[2];
    const float* b_qkv  = (const float*)d_in[3];
    const float* w_sa_o = (const float*)d_in[4];
    const float* b_sa_o = (const float*)d_in[5];
    const float* w_q    = (const float*)d_in[6];
    const float* b_q    = (const float*)d_in[7];
    const float* w_k    = (const float*)d_in[8];
    const float* b_k    = (const float*)d_in[9];
    const float* w_v    = (const float*)d_in[10];
    const float* b_v    = (const float*)d_in[11];
    const float* w_ca_o = (const float*)d_in[12];
    const float* b_ca_o = (const float*)d_in[13];
    const float* w1     = (const float*)d_in[14];
    const float* b1     = (const float*)d_in[15];
    const float* w2     = (const float*)d_in[16];
    const float* b2     = (const float*)d_in[17];
    const float* g1     = (const float*)d_in[18];
    const float* be1    = (const float*)d_in[19];
    const float* g2     = (const float*)d_in[20];
    const float* be2    = (const float*)d_in[21];
    const float* g3     = (const float*)d_in[22];
    const float* be3    = (const float*)d_in[23];
    float* out = (float*)d_out;

    float *p_tmp, *p_h1, *p_h2;
    cudaGetSymbolAddress((void**)&p_tmp,  g_tmp);
    cudaGetSymbolAddress((void**)&p_h1,   g_h1);
    cudaGetSymbolAddress((void**)&p_h2,   g_h2);

    __half *p_x16, *p_ex16, *p_qkv16, *p_attn16, *p_h16, *p_q16, *p_k16, *p_v16, *p_f116;
    __half *p_wqkvT, *p_wsaoT, *p_wqT, *p_wkT, *p_wvT, *p_wcaoT, *p_w1T, *p_w2T;
    cudaGetSymbolAddress((void**)&p_x16,    g_x16);
    cudaGetSymbolAddress((void**)&p_ex16,   g_ex16);
    cudaGetSymbolAddress((void**)&p_qkv16,  g_qkv16);
    cudaGetSymbolAddress((void**)&p_attn16, g_attn16);
    cudaGetSymbolAddress((void**)&p_h16,    g_h16);
    cudaGetSymbolAddress((void**)&p_q16,    g_q16);
    cudaGetSymbolAddress((void**)&p_k16,    g_k16);
    cudaGetSymbolAddress((void**)&p_v16,    g_v16);
    cudaGetSymbolAddress((void**)&p_f116,   g_f116);
    cudaGetSymbolAddress((void**)&p_wqkvT,  g_wqkvT);
    cudaGetSymbolAddress((void**)&p_wsaoT,  g_wsaoT);
    cudaGetSymbolAddress((void**)&p_wqT,    g_wqT);
    cudaGetSymbolAddress((void**)&p_wkT,    g_wkT);
    cudaGetSymbolAddress((void**)&p_wvT,    g_wvT);
    cudaGetSymbolAddress((void**)&p_wcaoT,  g_wcaoT);
    cudaGetSymbolAddress((void**)&p_w1T,    g_w1T);
    cudaGetSymbolAddress((void**)&p_w2T,    g_w2T);

    static int smem_set = 0;
    if (!smem_set) {
        cudaFuncSetAttribute(gemm_tc, cudaFuncAttributeMaxDynamicSharedMemorySize, GEMM_SMEM);
        smem_set = 1;
    }

    const dim3 blk256(256);
    const dim3 t32(32, 32);
    const dim3 fgrd(S_ / 64, B_ * H_);

    // ---- weight prep (transpose + fp16) ----
    transpose_f16_kernel<<<dim3(3 * D_ / 32, D_ / 32), t32>>>(w_qkv, p_wqkvT, D_, 3 * D_);
    transpose_f16_kernel<<<dim3(D_ / 32, D_ / 32), t32>>>(w_sa_o, p_wsaoT, D_, D_);
    transpose_f16_kernel<<<dim3(D_ / 32, D_ / 32), t32>>>(w_q, p_wqT, D_, D_);
    transpose_f16_kernel<<<dim3(D_ / 32, D_ / 32), t32>>>(w_k, p_wkT, D_, D_);
    transpose_f16_kernel<<<dim3(D_ / 32, D_ / 32), t32>>>(w_v, p_wvT, D_, D_);
    transpose_f16_kernel<<<dim3(D_ / 32, D_ / 32), t32>>>(w_ca_o, p_wcaoT, D_, D_);
    transpose_f16_kernel<<<dim3(DFF_ / 32, D_ / 32), t32>>>(w1, p_w1T, D_, DFF_);
    transpose_f16_kernel<<<dim3(D_ / 32, DFF_ / 32), t32>>>(w2, p_w2T, DFF_, D_);
    f32_to_f16_kernel<<<4096, blk256>>>(x, p_x16, MROWS * D_);
    f32_to_f16_kernel<<<4096, blk256>>>(enc_x, p_ex16, B_ * E_ * D_);

    // ---- masked self-attention ----
    gemm_tc<<<dim3(3 * D_ / TN, MROWS / TM), 256, GEMM_SMEM>>>(
        p_x16, p_wqkvT, b_qkv, (float*)0, p_qkv16, MROWS, 3 * D_, D_, 0);
    flash_kernel<<<fgrd, 128>>>(p_qkv16, p_qkv16, p_qkv16, p_attn16,
                                3 * D_, 3 * D_, 192, 192, 64, 128, 1);
    gemm_tc<<<dim3(D_ / TN, MROWS / TM), 256, GEMM_SMEM>>>(
        p_attn16, p_wsaoT, b_sa_o, p_tmp, (__half*)0, MROWS, D_, D_, 0);
    add_ln_kernel<<<MROWS, blk256>>>(x, p_tmp, g1, be1, p_h1, p_h16);

    // ---- cross-attention ----
    gemm_tc<<<dim3(D_ / TN, MROWS / TM), 256, GEMM_SMEM>>>(
        p_h16, p_wqT, b_q, (float*)0, p_q16, MROWS, D_, D_, 0);
    gemm_tc<<<dim3(D_ / TN, MROWS / TM), 256, GEMM_SMEM>>>(
        p_ex16, p_wkT, b_k, (float*)0, p_k16, B_ * E_, D_, D_, 0);
    gemm_tc<<<dim3(D_ / TN, MROWS / TM), 256, GEMM_SMEM>>>(
        p_ex16, p_wvT, b_v, (float*)0, p_v16, B_ * E_, D_, D_, 0);
    flash_kernel<<<fgrd, 128>>>(p_q16, p_k16, p_v16, p_attn16,
                                D_, D_, 64, 64, 0, 0, 0);
    gemm_tc<<<dim3(D_ / TN, MROWS / TM), 256, GEMM_SMEM>>>(
        p_attn16, p_wcaoT, b_ca_o, p_tmp, (__half*)0, MROWS, D_, D_, 0);
    add_ln_kernel<<<MROWS, blk256>>>(p_h1, p_tmp, g2, be2, p_h2, p_h16);

    // ---- FFN ----
    gemm_tc<<<dim3(DFF_ / TN, MROWS / TM), 256, GEMM_SMEM>>>(
        p_h16, p_w1T, b1, (float*)0, p_f116, MROWS, DFF_, D_, 1);
    gemm_tc<<<dim3(D_ / TN, MROWS / TM), 256, GEMM_SMEM>>>(
        p_f116, p_w2T, b2, p_tmp, (__half*)0, MROWS, D_, DFF_, 0);
    add_ln_kernel<<<MROWS, blk256>>>(p_h2, p_tmp, g3, be3, out, (__half*)0);
}